// round 1
// baseline (speedup 1.0000x reference)
#include <cuda_runtime.h>

#define BB 8
#define NN 8192
#define MM 1024
#define KK 32
#define CC 64
#define CIN 67
#define R2 0.16f

// scratch: ball-query neighbor indices
__device__ int g_gidx[BB * MM * KK];

// ---------------------------------------------------------------------------
// FPS: one block per batch, 1024 threads, 8 points per thread (strided).
// Replicates jnp.argmax tie-break (first/lowest index).
// ---------------------------------------------------------------------------
__global__ __launch_bounds__(1024, 1)
void fps_kernel(const float* __restrict__ xyz, float* __restrict__ newxyz) {
    int b = blockIdx.x;
    const float* x = xyz + (long)b * NN * 3;
    int tid = threadIdx.x;

    float px[8], py[8], pz[8], dd[8];
#pragma unroll
    for (int j = 0; j < 8; j++) {
        int p = j * 1024 + tid;
        px[j] = x[p * 3 + 0];
        py[j] = x[p * 3 + 1];
        pz[j] = x[p * 3 + 2];
        dd[j] = 1e10f;
    }

    __shared__ float sl[3];
    __shared__ float srd[32];
    __shared__ int sri[32];
    __shared__ int swin;

    if (tid == 0) {
        // first selected index is always 0
        sl[0] = px[0]; sl[1] = py[0]; sl[2] = pz[0];
        newxyz[(long)b * MM * 3 + 0] = px[0];
        newxyz[(long)b * MM * 3 + 1] = py[0];
        newxyz[(long)b * MM * 3 + 2] = pz[0];
    }
    __syncthreads();

    int lane = tid & 31;
    int wid = tid >> 5;

    for (int it = 1; it < MM; it++) {
        float lx = sl[0], ly = sl[1], lz = sl[2];
        float bd = -1.0f;
        int bi = 0;
#pragma unroll
        for (int j = 0; j < 8; j++) {
            float dx = px[j] - lx;
            float dy = py[j] - ly;
            float dz = pz[j] - lz;
            float d = fmaf(dx, dx, fmaf(dy, dy, dz * dz));
            float nd = fminf(dd[j], d);
            dd[j] = nd;
            if (nd > bd) { bd = nd; bi = j * 1024 + tid; }  // strict > keeps smallest idx
        }
        // warp argmax (tie -> smaller index)
#pragma unroll
        for (int off = 16; off; off >>= 1) {
            float od = __shfl_down_sync(0xffffffffu, bd, off);
            int oi = __shfl_down_sync(0xffffffffu, bi, off);
            if (od > bd || (od == bd && oi < bi)) { bd = od; bi = oi; }
        }
        if (lane == 0) { srd[wid] = bd; sri[wid] = bi; }
        __syncthreads();
        if (wid == 0) {
            bd = srd[lane];
            bi = sri[lane];
#pragma unroll
            for (int off = 16; off; off >>= 1) {
                float od = __shfl_down_sync(0xffffffffu, bd, off);
                int oi = __shfl_down_sync(0xffffffffu, bi, off);
                if (od > bd || (od == bd && oi < bi)) { bd = od; bi = oi; }
            }
            if (lane == 0) swin = bi;
        }
        __syncthreads();
        int w = swin;
        if ((w & 1023) == tid) {
            int j = w >> 10;
            sl[0] = px[j]; sl[1] = py[j]; sl[2] = pz[j];
            newxyz[(long)b * MM * 3 + it * 3 + 0] = px[j];
            newxyz[(long)b * MM * 3 + it * 3 + 1] = py[j];
            newxyz[(long)b * MM * 3 + it * 3 + 2] = pz[j];
        }
        __syncthreads();
    }
}

// ---------------------------------------------------------------------------
// Ball query: one warp per center. First-K in-radius (index order), pad with
// first hit. Early exit once K found.
// ---------------------------------------------------------------------------
__global__ __launch_bounds__(256)
void bq_kernel(const float* __restrict__ xyz, const float* __restrict__ newxyz,
               int* __restrict__ gidx) {
    int gw = blockIdx.x * 8 + (threadIdx.x >> 5);
    int lane = threadIdx.x & 31;
    int b = gw >> 10;
    const float* x = xyz + (long)b * NN * 3;
    float cx = newxyz[(long)gw * 3 + 0];
    float cy = newxyz[(long)gw * 3 + 1];
    float cz = newxyz[(long)gw * 3 + 2];
    int* out = g_gidx + (long)gw * KK;

    int cnt = 0;
    int first = 0;
    bool haveFirst = false;

    for (int ch = 0; ch < NN / 32 && cnt < KK; ch++) {
        int p = ch * 32 + lane;
        float dx = x[p * 3 + 0] - cx;
        float dy = x[p * 3 + 1] - cy;
        float dz = x[p * 3 + 2] - cz;
        float d2 = fmaf(dx, dx, fmaf(dy, dy, dz * dz));
        bool in = d2 < R2;
        unsigned mk = __ballot_sync(0xffffffffu, in);
        if (mk) {
            if (!haveFirst) { first = ch * 32 + __ffs(mk) - 1; haveFirst = true; }
            if (in) {
                int pos = cnt + __popc(mk & ((1u << lane) - 1u));
                if (pos < KK) out[pos] = p;
            }
            cnt += __popc(mk);
        }
    }
    for (int i = cnt + lane; i < KK; i += 32) out[i] = first;
    (void)gidx;
}

// ---------------------------------------------------------------------------
// Fused gather + 3-layer MLP + maxpool. Persistent blocks: weights loaded to
// SMEM once per block. 128 threads/block. Register tiles: 4x4 (L1,L2), 4x8 (L3)
// with float4 LDS operand loads.
// ---------------------------------------------------------------------------
__global__ __launch_bounds__(128)
void mlp_kernel(const float* __restrict__ xyz, const float* __restrict__ feat,
                const float* __restrict__ newxyz,
                const float* __restrict__ w1, const float* __restrict__ b1,
                const float* __restrict__ w2, const float* __restrict__ b2,
                const float* __restrict__ w3, const float* __restrict__ b3,
                float* __restrict__ outf) {
    extern __shared__ float sm[];
    float* sw1 = sm;                 // [67][64] = 4288
    float* sw2 = sw1 + CIN * 64;     // [64][64] = 4096
    float* sw3 = sw2 + 64 * 64;      // [64][128] = 8192
    float* sb1 = sw3 + 64 * 128;     // 64
    float* sb2 = sb1 + 64;           // 64
    float* sb3 = sb2 + 64;           // 128
    float* xin = sb3 + 128;          // [67][32] = 2144
    float* h1  = xin + CIN * 32;     // [64][32] = 2048
    __shared__ int sidx[KK];

    int tid = threadIdx.x;

    // load + transpose weights once ([o][c] -> [c][o])
    for (int i = tid; i < 64 * CIN; i += 128) sw1[(i % CIN) * 64 + (i / CIN)] = w1[i];
    for (int i = tid; i < 64 * 64; i += 128) sw2[(i & 63) * 64 + (i >> 6)] = w2[i];
    for (int i = tid; i < 128 * 64; i += 128) sw3[(i & 63) * 128 + (i >> 6)] = w3[i];
    if (tid < 64) { sb1[tid] = b1[tid]; sb2[tid] = b2[tid]; }
    sb3[tid] = b3[tid];
    __syncthreads();

    int s = tid >> 2, part = tid & 3;   // gather mapping
    int sg = tid & 7, og = tid >> 3;    // compute mapping
    int s0 = sg * 4;

    for (int g = blockIdx.x; g < BB * MM; g += gridDim.x) {
        int b = g >> 10, m = g & 1023;

        if (tid < KK) sidx[tid] = g_gidx[(long)g * KK + tid];
        __syncthreads();

        float cx = newxyz[(long)g * 3 + 0];
        float cy = newxyz[(long)g * 3 + 1];
        float cz = newxyz[(long)g * 3 + 2];

        // gather: each thread loads 16 features of one sample
        int pi = sidx[s];
        const float4* frow = (const float4*)(feat + ((long)b * NN + pi) * CC) + part * 4;
#pragma unroll
        for (int q = 0; q < 4; q++) {
            float4 v = frow[q];
            int c0 = 3 + part * 16 + q * 4;
            xin[(c0 + 0) * 32 + s] = v.x;
            xin[(c0 + 1) * 32 + s] = v.y;
            xin[(c0 + 2) * 32 + s] = v.z;
            xin[(c0 + 3) * 32 + s] = v.w;
        }
        if (part == 0) {
            const float* pr = xyz + ((long)b * NN + pi) * 3;
            xin[0 * 32 + s] = pr[0] - cx;
            xin[1 * 32 + s] = pr[1] - cy;
            xin[2 * 32 + s] = pr[2] - cz;
        }
        __syncthreads();

        // ---- layer 1: 67 -> 64 ----
        {
            int o0 = og * 4;
            float acc[4][4];
#pragma unroll
            for (int i = 0; i < 4; i++)
#pragma unroll
                for (int j = 0; j < 4; j++) acc[i][j] = 0.0f;
            for (int c = 0; c < CIN; c++) {
                float4 xv = *(const float4*)&xin[c * 32 + s0];
                float4 wv = *(const float4*)&sw1[c * 64 + o0];
                float xs[4] = {xv.x, xv.y, xv.z, xv.w};
                float ws[4] = {wv.x, wv.y, wv.z, wv.w};
#pragma unroll
                for (int i = 0; i < 4; i++)
#pragma unroll
                    for (int j = 0; j < 4; j++) acc[i][j] = fmaf(xs[i], ws[j], acc[i][j]);
            }
#pragma unroll
            for (int j = 0; j < 4; j++) {
                float bb = sb1[o0 + j];
                float4 r;
                r.x = fmaxf(acc[0][j] + bb, 0.0f);
                r.y = fmaxf(acc[1][j] + bb, 0.0f);
                r.z = fmaxf(acc[2][j] + bb, 0.0f);
                r.w = fmaxf(acc[3][j] + bb, 0.0f);
                *(float4*)&h1[(o0 + j) * 32 + s0] = r;
            }
        }
        __syncthreads();

        // ---- layer 2: 64 -> 64 (reads h1, writes xin) ----
        {
            int o0 = og * 4;
            float acc[4][4];
#pragma unroll
            for (int i = 0; i < 4; i++)
#pragma unroll
                for (int j = 0; j < 4; j++) acc[i][j] = 0.0f;
            for (int c = 0; c < 64; c++) {
                float4 xv = *(const float4*)&h1[c * 32 + s0];
                float4 wv = *(const float4*)&sw2[c * 64 + o0];
                float xs[4] = {xv.x, xv.y, xv.z, xv.w};
                float ws[4] = {wv.x, wv.y, wv.z, wv.w};
#pragma unroll
                for (int i = 0; i < 4; i++)
#pragma unroll
                    for (int j = 0; j < 4; j++) acc[i][j] = fmaf(xs[i], ws[j], acc[i][j]);
            }
#pragma unroll
            for (int j = 0; j < 4; j++) {
                float bb = sb2[o0 + j];
                float4 r;
                r.x = fmaxf(acc[0][j] + bb, 0.0f);
                r.y = fmaxf(acc[1][j] + bb, 0.0f);
                r.z = fmaxf(acc[2][j] + bb, 0.0f);
                r.w = fmaxf(acc[3][j] + bb, 0.0f);
                *(float4*)&xin[(o0 + j) * 32 + s0] = r;
            }
        }
        __syncthreads();

        // ---- layer 3: 64 -> 128, maxpool over samples ----
        {
            int oo = og * 8;
            float a3[4][8];
#pragma unroll
            for (int i = 0; i < 4; i++)
#pragma unroll
                for (int j = 0; j < 8; j++) a3[i][j] = 0.0f;
            for (int c = 0; c < 64; c++) {
                float4 xv = *(const float4*)&xin[c * 32 + s0];
                float4 wa = *(const float4*)&sw3[c * 128 + oo];
                float4 wb = *(const float4*)&sw3[c * 128 + oo + 4];
                float xs[4] = {xv.x, xv.y, xv.z, xv.w};
                float ws[8] = {wa.x, wa.y, wa.z, wa.w, wb.x, wb.y, wb.z, wb.w};
#pragma unroll
                for (int i = 0; i < 4; i++)
#pragma unroll
                    for (int j = 0; j < 8; j++) a3[i][j] = fmaf(xs[i], ws[j], a3[i][j]);
            }
            float mx[8];
#pragma unroll
            for (int j = 0; j < 8; j++) {
                float bb = sb3[oo + j];
                float v = fmaxf(a3[0][j] + bb, 0.0f);
                v = fmaxf(v, fmaxf(a3[1][j] + bb, 0.0f));
                v = fmaxf(v, fmaxf(a3[2][j] + bb, 0.0f));
                v = fmaxf(v, fmaxf(a3[3][j] + bb, 0.0f));
                mx[j] = v;
            }
            // reduce across the 8 sample-groups (lanes differing in bits 0..2)
#pragma unroll
            for (int off = 1; off < 8; off <<= 1) {
#pragma unroll
                for (int j = 0; j < 8; j++)
                    mx[j] = fmaxf(mx[j], __shfl_xor_sync(0xffffffffu, mx[j], off));
            }
            if (sg == 0) {
                float* op = outf + (long)b * 128 * 1024 + m;
#pragma unroll
                for (int j = 0; j < 8; j++) op[(long)(oo + j) * 1024] = mx[j];
            }
        }
        __syncthreads();
    }
}

// ---------------------------------------------------------------------------
extern "C" void kernel_launch(void* const* d_in, const int* in_sizes, int n_in,
                              void* d_out, int out_size) {
    const float* xyz = (const float*)d_in[0];
    const float* feat = (const float*)d_in[1];
    const float* w1 = (const float*)d_in[2];
    const float* b1 = (const float*)d_in[3];
    const float* w2 = (const float*)d_in[4];
    const float* b2 = (const float*)d_in[5];
    const float* w3 = (const float*)d_in[6];
    const float* b3 = (const float*)d_in[7];
    float* out = (float*)d_out;
    float* newxyz = out;                       // (B, M, 3)
    float* outf = out + (long)BB * MM * 3;     // (B, 128, M)

    fps_kernel<<<BB, 1024>>>(xyz, newxyz);
    bq_kernel<<<BB * MM / 8, 256>>>(xyz, newxyz, g_gidx);

    int smem = (CIN * 64 + 64 * 64 + 64 * 128 + 64 + 64 + 128 + CIN * 32 + 64 * 32) * 4;
    cudaFuncSetAttribute(mlp_kernel, cudaFuncAttributeMaxDynamicSharedMemorySize, smem);
    mlp_kernel<<<304, 128, smem>>>(xyz, feat, newxyz, w1, b1, w2, b2, w3, b3, outf);

    (void)in_sizes; (void)n_in; (void)out_size;
}

// round 3
// speedup vs baseline: 1.1223x; 1.1223x over previous
#include <cuda_runtime.h>

#define BB 8
#define NN 8192
#define MM 1024
#define KK 32
#define CC 64
#define CIN 67
#define R2 0.16f

// scratch: ball-query neighbor indices
__device__ int g_gidx[BB * MM * KK];

typedef unsigned long long ull;

// ---- packed f32x2 helpers (sm_100+: only add/mul/fma exist packed) ----
__device__ __forceinline__ ull pk2(float a, float b) {
    ull r; asm("mov.b64 %0,{%1,%2};" : "=l"(r) : "f"(a), "f"(b)); return r;
}
__device__ __forceinline__ void upk2(ull v, float& a, float& b) {
    asm("mov.b64 {%0,%1},%2;" : "=f"(a), "=f"(b) : "l"(v));
}
__device__ __forceinline__ ull add2(ull a, ull b) {
    ull r; asm("add.rn.f32x2 %0,%1,%2;" : "=l"(r) : "l"(a), "l"(b)); return r;
}
__device__ __forceinline__ ull mul2(ull a, ull b) {
    ull r; asm("mul.rn.f32x2 %0,%1,%2;" : "=l"(r) : "l"(a), "l"(b)); return r;
}
__device__ __forceinline__ ull fma2(ull a, ull b, ull c) {
    ull r; asm("fma.rn.f32x2 %0,%1,%2,%3;" : "=l"(r) : "l"(a), "l"(b), "l"(c)); return r;
}
// min/max: no packed PTX form -> scalar FMNMX pair (ALU pipe, overlaps FMA pipe)
__device__ __forceinline__ ull min2(ull a, ull b) {
    float al, ah, bl, bh; upk2(a, al, ah); upk2(b, bl, bh);
    return pk2(fminf(al, bl), fminf(ah, bh));
}
__device__ __forceinline__ ull max2(ull a, ull b) {
    float al, ah, bl, bh; upk2(a, al, ah); upk2(b, bl, bh);
    return pk2(fmaxf(al, bl), fmaxf(ah, bh));
}

// ---------------------------------------------------------------------------
// FPS: one block per batch, 1024 threads, 8 points per thread, packed f32x2.
// One __syncthreads per iteration; 64-bit key (distbits<<32 | 8191-idx) gives
// max-dist / min-index semantics identical to jnp.argmax.
// ---------------------------------------------------------------------------
__global__ __launch_bounds__(1024, 1)
void fps_kernel(const float* __restrict__ xyz, float* __restrict__ newxyz) {
    int b = blockIdx.x;
    const float* x = xyz + (long)b * NN * 3;
    int tid = threadIdx.x;
    int lane = tid & 31;
    int wid = tid >> 5;

    // pair jp holds points (2jp)*1024+tid (lo) and (2jp+1)*1024+tid (hi)
    ull pxp[4], pyp[4], pzp[4], ddp[4];
#pragma unroll
    for (int jp = 0; jp < 4; jp++) {
        int p0 = (2 * jp) * 1024 + tid;
        int p1 = (2 * jp + 1) * 1024 + tid;
        pxp[jp] = pk2(x[p0 * 3 + 0], x[p1 * 3 + 0]);
        pyp[jp] = pk2(x[p0 * 3 + 1], x[p1 * 3 + 1]);
        pzp[jp] = pk2(x[p0 * 3 + 2], x[p1 * 3 + 2]);
        ddp[jp] = pk2(1e10f, 1e10f);
    }

    __shared__ ull skey[2][32];

    float lx = __ldg(x + 0), ly = __ldg(x + 1), lz = __ldg(x + 2);
    if (tid == 0) {
        newxyz[(long)b * MM * 3 + 0] = lx;
        newxyz[(long)b * MM * 3 + 1] = ly;
        newxyz[(long)b * MM * 3 + 2] = lz;
    }

    for (int it = 1; it < MM; it++) {
        ull nlx = pk2(-lx, -lx), nly = pk2(-ly, -ly), nlz = pk2(-lz, -lz);
        ull bm = 0ull;  // packed (0,0); dists >= 0
#pragma unroll
        for (int jp = 0; jp < 4; jp++) {
            ull dx = add2(pxp[jp], nlx);
            ull dy = add2(pyp[jp], nly);
            ull dz = add2(pzp[jp], nlz);
            ull m = mul2(dz, dz);
            m = fma2(dy, dy, m);
            m = fma2(dx, dx, m);
            ddp[jp] = min2(ddp[jp], m);
            bm = max2(bm, ddp[jp]);
        }
        float b0, b1;
        upk2(bm, b0, b1);
        float bd = fmaxf(b0, b1);
        // recover smallest local index j with dd[j] == bd
        int bj = 0;
#pragma unroll
        for (int jp = 3; jp >= 0; jp--) {
            float lo, hi;
            upk2(ddp[jp], lo, hi);
            if (hi == bd) bj = 2 * jp + 1;
            if (lo == bd) bj = 2 * jp;
        }
        int gidx = bj * 1024 + tid;
        ull key = ((ull)__float_as_uint(bd) << 32) | (unsigned)(8191 - gidx);

        // warp reduce (max key)
#pragma unroll
        for (int off = 16; off; off >>= 1) {
            ull o = __shfl_down_sync(0xffffffffu, key, off);
            if (o > key) key = o;
        }
        int buf = it & 1;
        if (lane == 0) skey[buf][wid] = key;
        __syncthreads();

        // every warp redundantly reduces the 32 candidates (deterministic)
        ull k = skey[buf][lane];
#pragma unroll
        for (int off = 16; off; off >>= 1) {
            ull o = __shfl_down_sync(0xffffffffu, k, off);
            if (o > k) k = o;
        }
        k = __shfl_sync(0xffffffffu, k, 0);
        int w = 8191 - (int)(unsigned)(k & 0xffffffffull);

        lx = __ldg(x + w * 3 + 0);
        ly = __ldg(x + w * 3 + 1);
        lz = __ldg(x + w * 3 + 2);
        if (tid == 0) {
            newxyz[(long)b * MM * 3 + it * 3 + 0] = lx;
            newxyz[(long)b * MM * 3 + it * 3 + 1] = ly;
            newxyz[(long)b * MM * 3 + it * 3 + 2] = lz;
        }
    }
}

// ---------------------------------------------------------------------------
// Ball query: one warp per center. First-K in-radius, pad with first hit.
// ---------------------------------------------------------------------------
__global__ __launch_bounds__(256)
void bq_kernel(const float* __restrict__ xyz, const float* __restrict__ newxyz,
               int* __restrict__ gidx) {
    int gw = blockIdx.x * 8 + (threadIdx.x >> 5);
    int lane = threadIdx.x & 31;
    int b = gw >> 10;
    const float* x = xyz + (long)b * NN * 3;
    float cx = newxyz[(long)gw * 3 + 0];
    float cy = newxyz[(long)gw * 3 + 1];
    float cz = newxyz[(long)gw * 3 + 2];
    int* out = g_gidx + (long)gw * KK;

    int cnt = 0;
    int first = 0;
    bool haveFirst = false;

    for (int ch = 0; ch < NN / 32 && cnt < KK; ch++) {
        int p = ch * 32 + lane;
        float dx = x[p * 3 + 0] - cx;
        float dy = x[p * 3 + 1] - cy;
        float dz = x[p * 3 + 2] - cz;
        float d2 = fmaf(dx, dx, fmaf(dy, dy, dz * dz));
        bool in = d2 < R2;
        unsigned mk = __ballot_sync(0xffffffffu, in);
        if (mk) {
            if (!haveFirst) { first = ch * 32 + __ffs(mk) - 1; haveFirst = true; }
            if (in) {
                int pos = cnt + __popc(mk & ((1u << lane) - 1u));
                if (pos < KK) out[pos] = p;
            }
            cnt += __popc(mk);
        }
    }
    for (int i = cnt + lane; i < KK; i += 32) out[i] = first;
    (void)gidx;
}

// ---------------------------------------------------------------------------
// Fused gather + 3-layer MLP + maxpool, FFMA2 (f32x2) with j-packed weights.
// ---------------------------------------------------------------------------
__global__ __launch_bounds__(128)
void mlp_kernel(const float* __restrict__ xyz, const float* __restrict__ feat,
                const float* __restrict__ newxyz,
                const float* __restrict__ w1, const float* __restrict__ b1,
                const float* __restrict__ w2, const float* __restrict__ b2,
                const float* __restrict__ w3, const float* __restrict__ b3,
                float* __restrict__ outf) {
    extern __shared__ float sm[];
    float* sw1 = sm;                 // [67][64]
    float* sw2 = sw1 + CIN * 64;     // [64][64]
    float* sw3 = sw2 + 64 * 64;      // [64][128]
    float* sb1 = sw3 + 64 * 128;     // 64
    float* sb2 = sb1 + 64;           // 64
    float* sb3 = sb2 + 64;           // 128
    float* xin = sb3 + 128;          // [67][32]
    float* h1  = xin + CIN * 32;     // [64][32]
    __shared__ int sidx[KK];

    int tid = threadIdx.x;

    for (int i = tid; i < 64 * CIN; i += 128) sw1[(i % CIN) * 64 + (i / CIN)] = w1[i];
    for (int i = tid; i < 64 * 64; i += 128) sw2[(i & 63) * 64 + (i >> 6)] = w2[i];
    for (int i = tid; i < 128 * 64; i += 128) sw3[(i & 63) * 128 + (i >> 6)] = w3[i];
    if (tid < 64) { sb1[tid] = b1[tid]; sb2[tid] = b2[tid]; }
    sb3[tid] = b3[tid];
    __syncthreads();

    int s = tid >> 2, part = tid & 3;   // gather mapping
    int sg = tid & 7, og = tid >> 3;    // compute mapping
    int s0 = sg * 4;

    for (int g = blockIdx.x; g < BB * MM; g += gridDim.x) {
        int b = g >> 10, m = g & 1023;

        if (tid < KK) sidx[tid] = g_gidx[(long)g * KK + tid];
        __syncthreads();

        float cx = newxyz[(long)g * 3 + 0];
        float cy = newxyz[(long)g * 3 + 1];
        float cz = newxyz[(long)g * 3 + 2];

        int pi = sidx[s];
        const float4* frow = (const float4*)(feat + ((long)b * NN + pi) * CC) + part * 4;
#pragma unroll
        for (int q = 0; q < 4; q++) {
            float4 v = frow[q];
            int c0 = 3 + part * 16 + q * 4;
            xin[(c0 + 0) * 32 + s] = v.x;
            xin[(c0 + 1) * 32 + s] = v.y;
            xin[(c0 + 2) * 32 + s] = v.z;
            xin[(c0 + 3) * 32 + s] = v.w;
        }
        if (part == 0) {
            const float* pr = xyz + ((long)b * NN + pi) * 3;
            xin[0 * 32 + s] = pr[0] - cx;
            xin[1 * 32 + s] = pr[1] - cy;
            xin[2 * 32 + s] = pr[2] - cz;
        }
        __syncthreads();

        // ---- layer 1: 67 -> 64 (4 samples x 4 outputs, j-packed FFMA2) ----
        {
            int o0 = og * 4;
            ull acc[4][2];
#pragma unroll
            for (int i = 0; i < 4; i++) { acc[i][0] = 0ull; acc[i][1] = 0ull; }
            for (int c = 0; c < CIN; c++) {
                float4 xv = *(const float4*)&xin[c * 32 + s0];
                ulonglong2 wv = *(const ulonglong2*)&sw1[c * 64 + o0];
                ull xb[4] = {pk2(xv.x, xv.x), pk2(xv.y, xv.y), pk2(xv.z, xv.z), pk2(xv.w, xv.w)};
#pragma unroll
                for (int i = 0; i < 4; i++) {
                    acc[i][0] = fma2(xb[i], wv.x, acc[i][0]);
                    acc[i][1] = fma2(xb[i], wv.y, acc[i][1]);
                }
            }
            ull bp0 = *(const ull*)&sb1[o0];
            ull bp1 = *(const ull*)&sb1[o0 + 2];
            float f[4][4];
#pragma unroll
            for (int i = 0; i < 4; i++) {
                upk2(max2(add2(acc[i][0], bp0), 0ull), f[i][0], f[i][1]);
                upk2(max2(add2(acc[i][1], bp1), 0ull), f[i][2], f[i][3]);
            }
#pragma unroll
            for (int j = 0; j < 4; j++)
                *(float4*)&h1[(o0 + j) * 32 + s0] =
                    make_float4(f[0][j], f[1][j], f[2][j], f[3][j]);
        }
        __syncthreads();

        // ---- layer 2: 64 -> 64 ----
        {
            int o0 = og * 4;
            ull acc[4][2];
#pragma unroll
            for (int i = 0; i < 4; i++) { acc[i][0] = 0ull; acc[i][1] = 0ull; }
            for (int c = 0; c < 64; c++) {
                float4 xv = *(const float4*)&h1[c * 32 + s0];
                ulonglong2 wv = *(const ulonglong2*)&sw2[c * 64 + o0];
                ull xb[4] = {pk2(xv.x, xv.x), pk2(xv.y, xv.y), pk2(xv.z, xv.z), pk2(xv.w, xv.w)};
#pragma unroll
                for (int i = 0; i < 4; i++) {
                    acc[i][0] = fma2(xb[i], wv.x, acc[i][0]);
                    acc[i][1] = fma2(xb[i], wv.y, acc[i][1]);
                }
            }
            ull bp0 = *(const ull*)&sb2[o0];
            ull bp1 = *(const ull*)&sb2[o0 + 2];
            float f[4][4];
#pragma unroll
            for (int i = 0; i < 4; i++) {
                upk2(max2(add2(acc[i][0], bp0), 0ull), f[i][0], f[i][1]);
                upk2(max2(add2(acc[i][1], bp1), 0ull), f[i][2], f[i][3]);
            }
#pragma unroll
            for (int j = 0; j < 4; j++)
                *(float4*)&xin[(o0 + j) * 32 + s0] =
                    make_float4(f[0][j], f[1][j], f[2][j], f[3][j]);
        }
        __syncthreads();

        // ---- layer 3: 64 -> 128 (4 samples x 8 outputs), maxpool ----
        {
            int oo = og * 8;
            ull a3[4][4];
#pragma unroll
            for (int i = 0; i < 4; i++)
#pragma unroll
                for (int q = 0; q < 4; q++) a3[i][q] = 0ull;
            for (int c = 0; c < 64; c++) {
                float4 xv = *(const float4*)&xin[c * 32 + s0];
                ulonglong2 wa = *(const ulonglong2*)&sw3[c * 128 + oo];
                ulonglong2 wb = *(const ulonglong2*)&sw3[c * 128 + oo + 4];
                ull xb[4] = {pk2(xv.x, xv.x), pk2(xv.y, xv.y), pk2(xv.z, xv.z), pk2(xv.w, xv.w)};
#pragma unroll
                for (int i = 0; i < 4; i++) {
                    a3[i][0] = fma2(xb[i], wa.x, a3[i][0]);
                    a3[i][1] = fma2(xb[i], wa.y, a3[i][1]);
                    a3[i][2] = fma2(xb[i], wb.x, a3[i][2]);
                    a3[i][3] = fma2(xb[i], wb.y, a3[i][3]);
                }
            }
            ull mx[4];
#pragma unroll
            for (int q = 0; q < 4; q++) {
                ull bp = *(const ull*)&sb3[oo + 2 * q];
                ull v = max2(add2(a3[0][q], bp), 0ull);
                v = max2(v, max2(add2(a3[1][q], bp), 0ull));
                v = max2(v, max2(add2(a3[2][q], bp), 0ull));
                v = max2(v, max2(add2(a3[3][q], bp), 0ull));
                mx[q] = v;
            }
#pragma unroll
            for (int off = 1; off < 8; off <<= 1) {
#pragma unroll
                for (int q = 0; q < 4; q++) {
                    ull o = __shfl_xor_sync(0xffffffffu, mx[q], off);
                    mx[q] = max2(mx[q], o);
                }
            }
            if (sg == 0) {
                float* op = outf + (long)b * 128 * 1024 + m;
#pragma unroll
                for (int q = 0; q < 4; q++) {
                    float v0, v1;
                    upk2(mx[q], v0, v1);
                    op[(long)(oo + 2 * q) * 1024] = v0;
                    op[(long)(oo + 2 * q + 1) * 1024] = v1;
                }
            }
        }
        __syncthreads();
    }
}

// ---------------------------------------------------------------------------
extern "C" void kernel_launch(void* const* d_in, const int* in_sizes, int n_in,
                              void* d_out, int out_size) {
    const float* xyz = (const float*)d_in[0];
    const float* feat = (const float*)d_in[1];
    const float* w1 = (const float*)d_in[2];
    const float* b1 = (const float*)d_in[3];
    const float* w2 = (const float*)d_in[4];
    const float* b2 = (const float*)d_in[5];
    const float* w3 = (const float*)d_in[6];
    const float* b3 = (const float*)d_in[7];
    float* out = (float*)d_out;
    float* newxyz = out;                       // (B, M, 3)
    float* outf = out + (long)BB * MM * 3;     // (B, 128, M)

    fps_kernel<<<BB, 1024>>>(xyz, newxyz);
    bq_kernel<<<BB * MM / 8, 256>>>(xyz, newxyz, g_gidx);

    int smem = (CIN * 64 + 64 * 64 + 64 * 128 + 64 + 64 + 128 + CIN * 32 + 64 * 32) * 4;
    cudaFuncSetAttribute(mlp_kernel, cudaFuncAttributeMaxDynamicSharedMemorySize, smem);
    mlp_kernel<<<304, 128, smem>>>(xyz, feat, newxyz, w1, b1, w2, b2, w3, b3, outf);

    (void)in_sizes; (void)n_in; (void)out_size;
}

// round 4
// speedup vs baseline: 1.4182x; 1.2636x over previous
#include <cuda_runtime.h>

#define BB 8
#define NN 8192
#define MM 1024
#define KK 32
#define CC 64
#define CIN 67
#define R2 0.16f

// scratch: ball-query neighbor indices
__device__ int g_gidx[BB * MM * KK];

typedef unsigned long long ull;

// ---- packed f32x2 helpers (sm_100+: only add/mul/fma exist packed) ----
__device__ __forceinline__ ull pk2(float a, float b) {
    ull r; asm("mov.b64 %0,{%1,%2};" : "=l"(r) : "f"(a), "f"(b)); return r;
}
__device__ __forceinline__ void upk2(ull v, float& a, float& b) {
    asm("mov.b64 {%0,%1},%2;" : "=f"(a), "=f"(b) : "l"(v));
}
__device__ __forceinline__ ull add2(ull a, ull b) {
    ull r; asm("add.rn.f32x2 %0,%1,%2;" : "=l"(r) : "l"(a), "l"(b)); return r;
}
__device__ __forceinline__ ull mul2(ull a, ull b) {
    ull r; asm("mul.rn.f32x2 %0,%1,%2;" : "=l"(r) : "l"(a), "l"(b)); return r;
}
__device__ __forceinline__ ull fma2(ull a, ull b, ull c) {
    ull r; asm("fma.rn.f32x2 %0,%1,%2,%3;" : "=l"(r) : "l"(a), "l"(b), "l"(c)); return r;
}
// min/max: no packed PTX form -> scalar FMNMX pair (ALU pipe, overlaps FMA pipe)
__device__ __forceinline__ ull min2(ull a, ull b) {
    float al, ah, bl, bh; upk2(a, al, ah); upk2(b, bl, bh);
    return pk2(fminf(al, bl), fminf(ah, bh));
}
__device__ __forceinline__ ull max2(ull a, ull b) {
    float al, ah, bl, bh; upk2(a, al, ah); upk2(b, bl, bh);
    return pk2(fmaxf(al, bl), fmaxf(ah, bh));
}

// ---------------------------------------------------------------------------
// FPS: one block per batch, 1024 threads, 8 points per thread.
// Reduce 32-bit distances only (cheap); index resolved on the rare winner
// path via smem atomicMin (min global index == jnp.argmax tie-break).
// ---------------------------------------------------------------------------
__global__ __launch_bounds__(1024, 1)
void fps_kernel(const float* __restrict__ xyz, float* __restrict__ newxyz) {
    int b = blockIdx.x;
    const float* x = xyz + (long)b * NN * 3;
    int tid = threadIdx.x;
    int lane = tid & 31;
    int wid = tid >> 5;

    // pair jp holds points (2jp)*1024+tid (lo) and (2jp+1)*1024+tid (hi)
    ull pxp[4], pyp[4], pzp[4], ddp[4];
#pragma unroll
    for (int jp = 0; jp < 4; jp++) {
        int p0 = (2 * jp) * 1024 + tid;
        int p1 = (2 * jp + 1) * 1024 + tid;
        pxp[jp] = pk2(x[p0 * 3 + 0], x[p1 * 3 + 0]);
        pyp[jp] = pk2(x[p0 * 3 + 1], x[p1 * 3 + 1]);
        pzp[jp] = pk2(x[p0 * 3 + 2], x[p1 * 3 + 2]);
        ddp[jp] = pk2(1e10f, 1e10f);
    }

    __shared__ float swmax[2][32];
    __shared__ int swidx[2];

    if (tid == 0) { swidx[0] = 0x7fffffff; swidx[1] = 0x7fffffff; }

    float lx = __ldg(x + 0), ly = __ldg(x + 1), lz = __ldg(x + 2);
    if (tid == 0) {
        newxyz[(long)b * MM * 3 + 0] = lx;
        newxyz[(long)b * MM * 3 + 1] = ly;
        newxyz[(long)b * MM * 3 + 2] = lz;
    }
    __syncthreads();

    for (int it = 1; it < MM; it++) {
        int buf = it & 1;
        ull nlx = pk2(-lx, -lx), nly = pk2(-ly, -ly), nlz = pk2(-lz, -lz);
#pragma unroll
        for (int jp = 0; jp < 4; jp++) {
            ull dx = add2(pxp[jp], nlx);
            ull dy = add2(pyp[jp], nly);
            ull dz = add2(pzp[jp], nlz);
            ull m = mul2(dz, dz);
            m = fma2(dy, dy, m);
            m = fma2(dx, dx, m);
            ddp[jp] = min2(ddp[jp], m);
        }
        // per-thread max distance
        ull t01 = max2(ddp[0], ddp[1]);
        ull t23 = max2(ddp[2], ddp[3]);
        ull tm = max2(t01, t23);
        float m0, m1;
        upk2(tm, m0, m1);
        float bd = fmaxf(m0, m1);

        // warp reduce (float max, bfly -> all lanes agree)
        float wm = bd;
#pragma unroll
        for (int off = 16; off; off >>= 1)
            wm = fmaxf(wm, __shfl_xor_sync(0xffffffffu, wm, off));
        if (lane == 0) swmax[buf][wid] = wm;
        __syncthreads();

        // every warp reduces the 32 per-warp maxima (deterministic, all agree)
        float gbd = swmax[buf][lane];
#pragma unroll
        for (int off = 16; off; off >>= 1)
            gbd = fmaxf(gbd, __shfl_xor_sync(0xffffffffu, gbd, off));

        // rare path: thread(s) holding the winning distance publish min index
        if (bd == gbd) {
            int bj = 0;
#pragma unroll
            for (int jp = 3; jp >= 0; jp--) {
                float lo, hi;
                upk2(ddp[jp], lo, hi);
                if (hi == gbd) bj = 2 * jp + 1;
                if (lo == gbd) bj = 2 * jp;
            }
            atomicMin(&swidx[buf], bj * 1024 + tid);
        }
        __syncthreads();

        int w = swidx[buf];
        // reset the OTHER buffer (read in prev iter before this iter's bar1)
        if (tid == 0) swidx[buf ^ 1] = 0x7fffffff;

        lx = __ldg(x + w * 3 + 0);
        ly = __ldg(x + w * 3 + 1);
        lz = __ldg(x + w * 3 + 2);
        if (tid == 0) {
            newxyz[(long)b * MM * 3 + it * 3 + 0] = lx;
            newxyz[(long)b * MM * 3 + it * 3 + 1] = ly;
            newxyz[(long)b * MM * 3 + it * 3 + 2] = lz;
        }
    }
}

// ---------------------------------------------------------------------------
// Ball query: one warp per center. First-K in-radius, pad with first hit.
// ---------------------------------------------------------------------------
__global__ __launch_bounds__(256)
void bq_kernel(const float* __restrict__ xyz, const float* __restrict__ newxyz,
               int* __restrict__ gidx) {
    int gw = blockIdx.x * 8 + (threadIdx.x >> 5);
    int lane = threadIdx.x & 31;
    int b = gw >> 10;
    const float* x = xyz + (long)b * NN * 3;
    float cx = newxyz[(long)gw * 3 + 0];
    float cy = newxyz[(long)gw * 3 + 1];
    float cz = newxyz[(long)gw * 3 + 2];
    int* out = g_gidx + (long)gw * KK;

    int cnt = 0;
    int first = 0;
    bool haveFirst = false;

    for (int ch = 0; ch < NN / 32 && cnt < KK; ch++) {
        int p = ch * 32 + lane;
        float dx = x[p * 3 + 0] - cx;
        float dy = x[p * 3 + 1] - cy;
        float dz = x[p * 3 + 2] - cz;
        float d2 = fmaf(dx, dx, fmaf(dy, dy, dz * dz));
        bool in = d2 < R2;
        unsigned mk = __ballot_sync(0xffffffffu, in);
        if (mk) {
            if (!haveFirst) { first = ch * 32 + __ffs(mk) - 1; haveFirst = true; }
            if (in) {
                int pos = cnt + __popc(mk & ((1u << lane) - 1u));
                if (pos < KK) out[pos] = p;
            }
            cnt += __popc(mk);
        }
    }
    for (int i = cnt + lane; i < KK; i += 32) out[i] = first;
    (void)gidx;
}

// ---------------------------------------------------------------------------
// Fused gather + 3-layer MLP + maxpool, FFMA2 (f32x2) with j-packed weights.
// ---------------------------------------------------------------------------
__global__ __launch_bounds__(128)
void mlp_kernel(const float* __restrict__ xyz, const float* __restrict__ feat,
                const float* __restrict__ newxyz,
                const float* __restrict__ w1, const float* __restrict__ b1,
                const float* __restrict__ w2, const float* __restrict__ b2,
                const float* __restrict__ w3, const float* __restrict__ b3,
                float* __restrict__ outf) {
    extern __shared__ float sm[];
    float* sw1 = sm;                 // [67][64]
    float* sw2 = sw1 + CIN * 64;     // [64][64]
    float* sw3 = sw2 + 64 * 64;      // [64][128]
    float* sb1 = sw3 + 64 * 128;     // 64
    float* sb2 = sb1 + 64;           // 64
    float* sb3 = sb2 + 64;           // 128
    float* xin = sb3 + 128;          // [67][32]
    float* h1  = xin + CIN * 32;     // [64][32]
    __shared__ int sidx[KK];

    int tid = threadIdx.x;

    for (int i = tid; i < 64 * CIN; i += 128) sw1[(i % CIN) * 64 + (i / CIN)] = w1[i];
    for (int i = tid; i < 64 * 64; i += 128) sw2[(i & 63) * 64 + (i >> 6)] = w2[i];
    for (int i = tid; i < 128 * 64; i += 128) sw3[(i & 63) * 128 + (i >> 6)] = w3[i];
    if (tid < 64) { sb1[tid] = b1[tid]; sb2[tid] = b2[tid]; }
    sb3[tid] = b3[tid];
    __syncthreads();

    int s = tid >> 2, part = tid & 3;   // gather mapping
    int sg = tid & 7, og = tid >> 3;    // compute mapping
    int s0 = sg * 4;

    for (int g = blockIdx.x; g < BB * MM; g += gridDim.x) {
        int b = g >> 10, m = g & 1023;

        if (tid < KK) sidx[tid] = g_gidx[(long)g * KK + tid];
        __syncthreads();

        float cx = newxyz[(long)g * 3 + 0];
        float cy = newxyz[(long)g * 3 + 1];
        float cz = newxyz[(long)g * 3 + 2];

        int pi = sidx[s];
        const float4* frow = (const float4*)(feat + ((long)b * NN + pi) * CC) + part * 4;
#pragma unroll
        for (int q = 0; q < 4; q++) {
            float4 v = frow[q];
            int c0 = 3 + part * 16 + q * 4;
            xin[(c0 + 0) * 32 + s] = v.x;
            xin[(c0 + 1) * 32 + s] = v.y;
            xin[(c0 + 2) * 32 + s] = v.z;
            xin[(c0 + 3) * 32 + s] = v.w;
        }
        if (part == 0) {
            const float* pr = xyz + ((long)b * NN + pi) * 3;
            xin[0 * 32 + s] = pr[0] - cx;
            xin[1 * 32 + s] = pr[1] - cy;
            xin[2 * 32 + s] = pr[2] - cz;
        }
        __syncthreads();

        // ---- layer 1: 67 -> 64 (4 samples x 4 outputs, j-packed FFMA2) ----
        {
            int o0 = og * 4;
            ull acc[4][2];
#pragma unroll
            for (int i = 0; i < 4; i++) { acc[i][0] = 0ull; acc[i][1] = 0ull; }
            for (int c = 0; c < CIN; c++) {
                float4 xv = *(const float4*)&xin[c * 32 + s0];
                ulonglong2 wv = *(const ulonglong2*)&sw1[c * 64 + o0];
                ull xb[4] = {pk2(xv.x, xv.x), pk2(xv.y, xv.y), pk2(xv.z, xv.z), pk2(xv.w, xv.w)};
#pragma unroll
                for (int i = 0; i < 4; i++) {
                    acc[i][0] = fma2(xb[i], wv.x, acc[i][0]);
                    acc[i][1] = fma2(xb[i], wv.y, acc[i][1]);
                }
            }
            ull bp0 = *(const ull*)&sb1[o0];
            ull bp1 = *(const ull*)&sb1[o0 + 2];
            float f[4][4];
#pragma unroll
            for (int i = 0; i < 4; i++) {
                upk2(max2(add2(acc[i][0], bp0), 0ull), f[i][0], f[i][1]);
                upk2(max2(add2(acc[i][1], bp1), 0ull), f[i][2], f[i][3]);
            }
#pragma unroll
            for (int j = 0; j < 4; j++)
                *(float4*)&h1[(o0 + j) * 32 + s0] =
                    make_float4(f[0][j], f[1][j], f[2][j], f[3][j]);
        }
        __syncthreads();

        // ---- layer 2: 64 -> 64 ----
        {
            int o0 = og * 4;
            ull acc[4][2];
#pragma unroll
            for (int i = 0; i < 4; i++) { acc[i][0] = 0ull; acc[i][1] = 0ull; }
            for (int c = 0; c < 64; c++) {
                float4 xv = *(const float4*)&h1[c * 32 + s0];
                ulonglong2 wv = *(const ulonglong2*)&sw2[c * 64 + o0];
                ull xb[4] = {pk2(xv.x, xv.x), pk2(xv.y, xv.y), pk2(xv.z, xv.z), pk2(xv.w, xv.w)};
#pragma unroll
                for (int i = 0; i < 4; i++) {
                    acc[i][0] = fma2(xb[i], wv.x, acc[i][0]);
                    acc[i][1] = fma2(xb[i], wv.y, acc[i][1]);
                }
            }
            ull bp0 = *(const ull*)&sb2[o0];
            ull bp1 = *(const ull*)&sb2[o0 + 2];
            float f[4][4];
#pragma unroll
            for (int i = 0; i < 4; i++) {
                upk2(max2(add2(acc[i][0], bp0), 0ull), f[i][0], f[i][1]);
                upk2(max2(add2(acc[i][1], bp1), 0ull), f[i][2], f[i][3]);
            }
#pragma unroll
            for (int j = 0; j < 4; j++)
                *(float4*)&xin[(o0 + j) * 32 + s0] =
                    make_float4(f[0][j], f[1][j], f[2][j], f[3][j]);
        }
        __syncthreads();

        // ---- layer 3: 64 -> 128 (4 samples x 8 outputs), maxpool ----
        {
            int oo = og * 8;
            ull a3[4][4];
#pragma unroll
            for (int i = 0; i < 4; i++)
#pragma unroll
                for (int q = 0; q < 4; q++) a3[i][q] = 0ull;
            for (int c = 0; c < 64; c++) {
                float4 xv = *(const float4*)&xin[c * 32 + s0];
                ulonglong2 wa = *(const ulonglong2*)&sw3[c * 128 + oo];
                ulonglong2 wb = *(const ulonglong2*)&sw3[c * 128 + oo + 4];
                ull xb[4] = {pk2(xv.x, xv.x), pk2(xv.y, xv.y), pk2(xv.z, xv.z), pk2(xv.w, xv.w)};
#pragma unroll
                for (int i = 0; i < 4; i++) {
                    a3[i][0] = fma2(xb[i], wa.x, a3[i][0]);
                    a3[i][1] = fma2(xb[i], wa.y, a3[i][1]);
                    a3[i][2] = fma2(xb[i], wb.x, a3[i][2]);
                    a3[i][3] = fma2(xb[i], wb.y, a3[i][3]);
                }
            }
            ull mx[4];
#pragma unroll
            for (int q = 0; q < 4; q++) {
                ull bp = *(const ull*)&sb3[oo + 2 * q];
                ull v = max2(add2(a3[0][q], bp), 0ull);
                v = max2(v, max2(add2(a3[1][q], bp), 0ull));
                v = max2(v, max2(add2(a3[2][q], bp), 0ull));
                v = max2(v, max2(add2(a3[3][q], bp), 0ull));
                mx[q] = v;
            }
#pragma unroll
            for (int off = 1; off < 8; off <<= 1) {
#pragma unroll
                for (int q = 0; q < 4; q++) {
                    ull o = __shfl_xor_sync(0xffffffffu, mx[q], off);
                    mx[q] = max2(mx[q], o);
                }
            }
            if (sg == 0) {
                float* op = outf + (long)b * 128 * 1024 + m;
#pragma unroll
                for (int q = 0; q < 4; q++) {
                    float v0, v1;
                    upk2(mx[q], v0, v1);
                    op[(long)(oo + 2 * q) * 1024] = v0;
                    op[(long)(oo + 2 * q + 1) * 1024] = v1;
                }
            }
        }
        __syncthreads();
    }
}

// ---------------------------------------------------------------------------
extern "C" void kernel_launch(void* const* d_in, const int* in_sizes, int n_in,
                              void* d_out, int out_size) {
    const float* xyz = (const float*)d_in[0];
    const float* feat = (const float*)d_in[1];
    const float* w1 = (const float*)d_in[2];
    const float* b1 = (const float*)d_in[3];
    const float* w2 = (const float*)d_in[4];
    const float* b2 = (const float*)d_in[5];
    const float* w3 = (const float*)d_in[6];
    const float* b3 = (const float*)d_in[7];
    float* out = (float*)d_out;
    float* newxyz = out;                       // (B, M, 3)
    float* outf = out + (long)BB * MM * 3;     // (B, 128, M)

    fps_kernel<<<BB, 1024>>>(xyz, newxyz);
    bq_kernel<<<BB * MM / 8, 256>>>(xyz, newxyz, g_gidx);

    int smem = (CIN * 64 + 64 * 64 + 64 * 128 + 64 + 64 + 128 + CIN * 32 + 64 * 32) * 4;
    cudaFuncSetAttribute(mlp_kernel, cudaFuncAttributeMaxDynamicSharedMemorySize, smem);
    mlp_kernel<<<304, 128, smem>>>(xyz, feat, newxyz, w1, b1, w2, b2, w3, b3, outf);

    (void)in_sizes; (void)n_in; (void)out_size;
}

// round 7
// speedup vs baseline: 1.7185x; 1.2117x over previous
#include <cuda_runtime.h>

#define BB 8
#define NN 8192
#define MM 1024
#define KK 32
#define CC 64
#define CIN 67
#define R2 0.16f

// scratch: ball-query neighbor indices
__device__ int g_gidx[BB * MM * KK];

typedef unsigned long long ull;

// ---- packed f32x2 helpers (sm_100+: only add/mul/fma exist packed) ----
__device__ __forceinline__ ull pk2(float a, float b) {
    ull r; asm("mov.b64 %0,{%1,%2};" : "=l"(r) : "f"(a), "f"(b)); return r;
}
__device__ __forceinline__ void upk2(ull v, float& a, float& b) {
    asm("mov.b64 {%0,%1},%2;" : "=f"(a), "=f"(b) : "l"(v));
}
__device__ __forceinline__ ull add2(ull a, ull b) {
    ull r; asm("add.rn.f32x2 %0,%1,%2;" : "=l"(r) : "l"(a), "l"(b)); return r;
}
__device__ __forceinline__ ull mul2(ull a, ull b) {
    ull r; asm("mul.rn.f32x2 %0,%1,%2;" : "=l"(r) : "l"(a), "l"(b)); return r;
}
__device__ __forceinline__ ull fma2(ull a, ull b, ull c) {
    ull r; asm("fma.rn.f32x2 %0,%1,%2,%3;" : "=l"(r) : "l"(a), "l"(b), "l"(c)); return r;
}
// min/max: no packed PTX form -> scalar FMNMX pair
__device__ __forceinline__ ull min2(ull a, ull b) {
    float al, ah, bl, bh; upk2(a, al, ah); upk2(b, bl, bh);
    return pk2(fminf(al, bl), fminf(ah, bh));
}
__device__ __forceinline__ ull max2(ull a, ull b) {
    float al, ah, bl, bh; upk2(a, al, ah); upk2(b, bl, bh);
    return pk2(fmaxf(al, bl), fmaxf(ah, bh));
}

// ---------------------------------------------------------------------------
// FPS: one block per batch, 1024 threads, 8 points per thread.
// Distances are nonneg -> u32 bit pattern is monotone: both reduction levels
// use single-instruction redux.sync.max.u32. Winner index resolved on the
// rare path via smem atomicMin (min global index == jnp.argmax tie-break).
// ---------------------------------------------------------------------------
__global__ __launch_bounds__(1024, 1)
void fps_kernel(const float* __restrict__ xyz, float* __restrict__ newxyz) {
    int b = blockIdx.x;
    const float* x = xyz + (long)b * NN * 3;
    int tid = threadIdx.x;
    int lane = tid & 31;
    int wid = tid >> 5;

    // pair jp holds points (2jp)*1024+tid (lo) and (2jp+1)*1024+tid (hi)
    ull pxp[4], pyp[4], pzp[4], ddp[4];
#pragma unroll
    for (int jp = 0; jp < 4; jp++) {
        int p0 = (2 * jp) * 1024 + tid;
        int p1 = (2 * jp + 1) * 1024 + tid;
        pxp[jp] = pk2(x[p0 * 3 + 0], x[p1 * 3 + 0]);
        pyp[jp] = pk2(x[p0 * 3 + 1], x[p1 * 3 + 1]);
        pzp[jp] = pk2(x[p0 * 3 + 2], x[p1 * 3 + 2]);
        ddp[jp] = pk2(1e10f, 1e10f);
    }

    __shared__ unsigned swmax[2][32];
    __shared__ int swidx[2];

    if (tid == 0) { swidx[0] = 0x7fffffff; swidx[1] = 0x7fffffff; }

    float lx = __ldg(x + 0), ly = __ldg(x + 1), lz = __ldg(x + 2);
    if (tid == 0) {
        newxyz[(long)b * MM * 3 + 0] = lx;
        newxyz[(long)b * MM * 3 + 1] = ly;
        newxyz[(long)b * MM * 3 + 2] = lz;
    }
    __syncthreads();

    for (int it = 1; it < MM; it++) {
        int buf = it & 1;
        ull nlx = pk2(-lx, -lx), nly = pk2(-ly, -ly), nlz = pk2(-lz, -lz);
#pragma unroll
        for (int jp = 0; jp < 4; jp++) {
            ull dx = add2(pxp[jp], nlx);
            ull dy = add2(pyp[jp], nly);
            ull dz = add2(pzp[jp], nlz);
            ull m = mul2(dz, dz);
            m = fma2(dy, dy, m);
            m = fma2(dx, dx, m);
            ddp[jp] = min2(ddp[jp], m);
        }
        // per-thread max distance
        ull t01 = max2(ddp[0], ddp[1]);
        ull t23 = max2(ddp[2], ddp[3]);
        ull tm = max2(t01, t23);
        float m0, m1;
        upk2(tm, m0, m1);
        unsigned bdu = __float_as_uint(fmaxf(m0, m1));

        // warp reduce: one REDUX (bits of nonneg float are monotone)
        unsigned wm = __reduce_max_sync(0xffffffffu, bdu);
        if (lane == 0) swmax[buf][wid] = wm;
        __syncthreads();

        // block reduce: every warp reduces the 32 per-warp maxima (1 REDUX)
        unsigned gb = __reduce_max_sync(0xffffffffu, swmax[buf][lane]);

        // rare path: thread(s) holding the winning distance publish min index
        if (bdu == gb) {
            int bj = 0;
#pragma unroll
            for (int jp = 3; jp >= 0; jp--) {
                float lo, hi;
                upk2(ddp[jp], lo, hi);
                if (__float_as_uint(hi) == gb) bj = 2 * jp + 1;
                if (__float_as_uint(lo) == gb) bj = 2 * jp;
            }
            atomicMin(&swidx[buf], bj * 1024 + tid);
        }
        __syncthreads();

        int w = swidx[buf];
        // reset the OTHER buffer (race-free window)
        if (tid == 0) swidx[buf ^ 1] = 0x7fffffff;

        lx = __ldg(x + w * 3 + 0);
        ly = __ldg(x + w * 3 + 1);
        lz = __ldg(x + w * 3 + 2);
        if (tid == 0) {
            newxyz[(long)b * MM * 3 + it * 3 + 0] = lx;
            newxyz[(long)b * MM * 3 + it * 3 + 1] = ly;
            newxyz[(long)b * MM * 3 + it * 3 + 2] = lz;
        }
    }
}

// ---------------------------------------------------------------------------
// Ball query: one warp per center. First-K in-radius, pad with first hit.
// ---------------------------------------------------------------------------
__global__ __launch_bounds__(256)
void bq_kernel(const float* __restrict__ xyz, const float* __restrict__ newxyz,
               int* __restrict__ gidx) {
    int gw = blockIdx.x * 8 + (threadIdx.x >> 5);
    int lane = threadIdx.x & 31;
    int b = gw >> 10;
    const float* x = xyz + (long)b * NN * 3;
    float cx = newxyz[(long)gw * 3 + 0];
    float cy = newxyz[(long)gw * 3 + 1];
    float cz = newxyz[(long)gw * 3 + 2];
    int* out = g_gidx + (long)gw * KK;

    int cnt = 0;
    int first = 0;
    bool haveFirst = false;

    for (int ch = 0; ch < NN / 32 && cnt < KK; ch++) {
        int p = ch * 32 + lane;
        float dx = x[p * 3 + 0] - cx;
        float dy = x[p * 3 + 1] - cy;
        float dz = x[p * 3 + 2] - cz;
        float d2 = fmaf(dx, dx, fmaf(dy, dy, dz * dz));
        bool in = d2 < R2;
        unsigned mk = __ballot_sync(0xffffffffu, in);
        if (mk) {
            if (!haveFirst) { first = ch * 32 + __ffs(mk) - 1; haveFirst = true; }
            if (in) {
                int pos = cnt + __popc(mk & ((1u << lane) - 1u));
                if (pos < KK) out[pos] = p;
            }
            cnt += __popc(mk);
        }
    }
    for (int i = cnt + lane; i < KK; i += 32) out[i] = first;
    (void)gidx;
}

// ---------------------------------------------------------------------------
// Fused gather + 3-layer MLP + maxpool, FFMA2 (f32x2) with j-packed weights.
// ---------------------------------------------------------------------------
__global__ __launch_bounds__(128)
void mlp_kernel(const float* __restrict__ xyz, const float* __restrict__ feat,
                const float* __restrict__ newxyz,
                const float* __restrict__ w1, const float* __restrict__ b1,
                const float* __restrict__ w2, const float* __restrict__ b2,
                const float* __restrict__ w3, const float* __restrict__ b3,
                float* __restrict__ outf) {
    extern __shared__ float sm[];
    float* sw1 = sm;                 // [67][64]
    float* sw2 = sw1 + CIN * 64;     // [64][64]
    float* sw3 = sw2 + 64 * 64;      // [64][128]
    float* sb1 = sw3 + 64 * 128;     // 64
    float* sb2 = sb1 + 64;           // 64
    float* sb3 = sb2 + 64;           // 128
    float* xin = sb3 + 128;          // [67][32]
    float* h1  = xin + CIN * 32;     // [64][32]
    __shared__ int sidx[KK];

    int tid = threadIdx.x;

    for (int i = tid; i < 64 * CIN; i += 128) sw1[(i % CIN) * 64 + (i / CIN)] = w1[i];
    for (int i = tid; i < 64 * 64; i += 128) sw2[(i & 63) * 64 + (i >> 6)] = w2[i];
    for (int i = tid; i < 128 * 64; i += 128) sw3[(i & 63) * 128 + (i >> 6)] = w3[i];
    if (tid < 64) { sb1[tid] = b1[tid]; sb2[tid] = b2[tid]; }
    sb3[tid] = b3[tid];
    __syncthreads();

    int s = tid >> 2, part = tid & 3;   // gather mapping
    int sg = tid & 7, og = tid >> 3;    // compute mapping
    int s0 = sg * 4;

    for (int g = blockIdx.x; g < BB * MM; g += gridDim.x) {
        int b = g >> 10, m = g & 1023;

        if (tid < KK) sidx[tid] = g_gidx[(long)g * KK + tid];
        __syncthreads();

        float cx = newxyz[(long)g * 3 + 0];
        float cy = newxyz[(long)g * 3 + 1];
        float cz = newxyz[(long)g * 3 + 2];

        int pi = sidx[s];
        const float4* frow = (const float4*)(feat + ((long)b * NN + pi) * CC) + part * 4;
#pragma unroll
        for (int q = 0; q < 4; q++) {
            float4 v = frow[q];
            int c0 = 3 + part * 16 + q * 4;
            xin[(c0 + 0) * 32 + s] = v.x;
            xin[(c0 + 1) * 32 + s] = v.y;
            xin[(c0 + 2) * 32 + s] = v.z;
            xin[(c0 + 3) * 32 + s] = v.w;
        }
        if (part == 0) {
            const float* pr = xyz + ((long)b * NN + pi) * 3;
            xin[0 * 32 + s] = pr[0] - cx;
            xin[1 * 32 + s] = pr[1] - cy;
            xin[2 * 32 + s] = pr[2] - cz;
        }
        __syncthreads();

        // ---- layer 1: 67 -> 64 (4 samples x 4 outputs, j-packed FFMA2) ----
        {
            int o0 = og * 4;
            ull acc[4][2];
#pragma unroll
            for (int i = 0; i < 4; i++) { acc[i][0] = 0ull; acc[i][1] = 0ull; }
            for (int c = 0; c < CIN; c++) {
                float4 xv = *(const float4*)&xin[c * 32 + s0];
                ulonglong2 wv = *(const ulonglong2*)&sw1[c * 64 + o0];
                ull xb[4] = {pk2(xv.x, xv.x), pk2(xv.y, xv.y), pk2(xv.z, xv.z), pk2(xv.w, xv.w)};
#pragma unroll
                for (int i = 0; i < 4; i++) {
                    acc[i][0] = fma2(xb[i], wv.x, acc[i][0]);
                    acc[i][1] = fma2(xb[i], wv.y, acc[i][1]);
                }
            }
            ull bp0 = *(const ull*)&sb1[o0];
            ull bp1 = *(const ull*)&sb1[o0 + 2];
            float f[4][4];
#pragma unroll
            for (int i = 0; i < 4; i++) {
                upk2(max2(add2(acc[i][0], bp0), 0ull), f[i][0], f[i][1]);
                upk2(max2(add2(acc[i][1], bp1), 0ull), f[i][2], f[i][3]);
            }
#pragma unroll
            for (int j = 0; j < 4; j++)
                *(float4*)&h1[(o0 + j) * 32 + s0] =
                    make_float4(f[0][j], f[1][j], f[2][j], f[3][j]);
        }
        __syncthreads();

        // ---- layer 2: 64 -> 64 ----
        {
            int o0 = og * 4;
            ull acc[4][2];
#pragma unroll
            for (int i = 0; i < 4; i++) { acc[i][0] = 0ull; acc[i][1] = 0ull; }
            for (int c = 0; c < 64; c++) {
                float4 xv = *(const float4*)&h1[c * 32 + s0];
                ulonglong2 wv = *(const ulonglong2*)&sw2[c * 64 + o0];
                ull xb[4] = {pk2(xv.x, xv.x), pk2(xv.y, xv.y), pk2(xv.z, xv.z), pk2(xv.w, xv.w)};
#pragma unroll
                for (int i = 0; i < 4; i++) {
                    acc[i][0] = fma2(xb[i], wv.x, acc[i][0]);
                    acc[i][1] = fma2(xb[i], wv.y, acc[i][1]);
                }
            }
            ull bp0 = *(const ull*)&sb2[o0];
            ull bp1 = *(const ull*)&sb2[o0 + 2];
            float f[4][4];
#pragma unroll
            for (int i = 0; i < 4; i++) {
                upk2(max2(add2(acc[i][0], bp0), 0ull), f[i][0], f[i][1]);
                upk2(max2(add2(acc[i][1], bp1), 0ull), f[i][2], f[i][3]);
            }
#pragma unroll
            for (int j = 0; j < 4; j++)
                *(float4*)&xin[(o0 + j) * 32 + s0] =
                    make_float4(f[0][j], f[1][j], f[2][j], f[3][j]);
        }
        __syncthreads();

        // ---- layer 3: 64 -> 128 (4 samples x 8 outputs), maxpool ----
        {
            int oo = og * 8;
            ull a3[4][4];
#pragma unroll
            for (int i = 0; i < 4; i++)
#pragma unroll
                for (int q = 0; q < 4; q++) a3[i][q] = 0ull;
            for (int c = 0; c < 64; c++) {
                float4 xv = *(const float4*)&xin[c * 32 + s0];
                ulonglong2 wa = *(const ulonglong2*)&sw3[c * 128 + oo];
                ulonglong2 wb = *(const ulonglong2*)&sw3[c * 128 + oo + 4];
                ull xb[4] = {pk2(xv.x, xv.x), pk2(xv.y, xv.y), pk2(xv.z, xv.z), pk2(xv.w, xv.w)};
#pragma unroll
                for (int i = 0; i < 4; i++) {
                    a3[i][0] = fma2(xb[i], wa.x, a3[i][0]);
                    a3[i][1] = fma2(xb[i], wa.y, a3[i][1]);
                    a3[i][2] = fma2(xb[i], wb.x, a3[i][2]);
                    a3[i][3] = fma2(xb[i], wb.y, a3[i][3]);
                }
            }
            ull mx[4];
#pragma unroll
            for (int q = 0; q < 4; q++) {
                ull bp = *(const ull*)&sb3[oo + 2 * q];
                ull v = max2(add2(a3[0][q], bp), 0ull);
                v = max2(v, max2(add2(a3[1][q], bp), 0ull));
                v = max2(v, max2(add2(a3[2][q], bp), 0ull));
                v = max2(v, max2(add2(a3[3][q], bp), 0ull));
                mx[q] = v;
            }
#pragma unroll
            for (int off = 1; off < 8; off <<= 1) {
#pragma unroll
                for (int q = 0; q < 4; q++) {
                    ull o = __shfl_xor_sync(0xffffffffu, mx[q], off);
                    mx[q] = max2(mx[q], o);
                }
            }
            if (sg == 0) {
                float* op = outf + (long)b * 128 * 1024 + m;
#pragma unroll
                for (int q = 0; q < 4; q++) {
                    float v0, v1;
                    upk2(mx[q], v0, v1);
                    op[(long)(oo + 2 * q) * 1024] = v0;
                    op[(long)(oo + 2 * q + 1) * 1024] = v1;
                }
            }
        }
        __syncthreads();
    }
}

// ---------------------------------------------------------------------------
extern "C" void kernel_launch(void* const* d_in, const int* in_sizes, int n_in,
                              void* d_out, int out_size) {
    const float* xyz = (const float*)d_in[0];
    const float* feat = (const float*)d_in[1];
    const float* w1 = (const float*)d_in[2];
    const float* b1 = (const float*)d_in[3];
    const float* w2 = (const float*)d_in[4];
    const float* b2 = (const float*)d_in[5];
    const float* w3 = (const float*)d_in[6];
    const float* b3 = (const float*)d_in[7];
    float* out = (float*)d_out;
    float* newxyz = out;                       // (B, M, 3)
    float* outf = out + (long)BB * MM * 3;     // (B, 128, M)

    fps_kernel<<<BB, 1024>>>(xyz, newxyz);
    bq_kernel<<<BB * MM / 8, 256>>>(xyz, newxyz, g_gidx);

    int smem = (CIN * 64 + 64 * 64 + 64 * 128 + 64 + 64 + 128 + CIN * 32 + 64 * 32) * 4;
    cudaFuncSetAttribute(mlp_kernel, cudaFuncAttributeMaxDynamicSharedMemorySize, smem);
    mlp_kernel<<<304, 128, smem>>>(xyz, feat, newxyz, w1, b1, w2, b2, w3, b3, outf);

    (void)in_sizes; (void)n_in; (void)out_size;
}